// round 7
// baseline (speedup 1.0000x reference)
#include <cuda_runtime.h>
#include <cuda_bf16.h>
#include <stdint.h>

// Problem constants
#define TT 6
#define BB 8
#define CC 192
#define HH 112
#define WW 112
#define KK 3
#define H0 56
#define W0 56
#define HWPIX (HH*WW)          // 12544
#define PIX (H0*W0)            // 3136
#define NN (TT*KK)             // 18 nodes
#define CG 8                   // channels per block in streaming kernels
#define NPOOLB (TT*BB*(CC/CG)) // 1152 pool blocks

// Scratch (static device globals — no allocation)
__device__ float g_feat[BB*NN*CC];          // node features [B][N=T*K][C]
__device__ float g_Wc[CC*CC];               // W_emb^T @ W_gcn

// ---------------------------------------------------------------------------
// Kernel 1: pool ∥ wc in one launch; wc blocks at the grid TAIL so they fill
// the final partial wave instead of displacing pool's first wave.
// blocks [0, NPOOLB):          masked adaptive pooling (exact R2 structure)
// blocks [NPOOLB, NPOOLB+CC):  Wc[c][e] = sum_d W_emb[d][c] * W_gcn[d][e]
__global__ __launch_bounds__(256) void poolwc_kernel(const float* __restrict__ x,
                                                     const int* __restrict__ masks,
                                                     const float* __restrict__ W_emb,
                                                     const float* __restrict__ W_gcn) {
    __shared__ float mf[3][PIX];      // pool masks; wc reuses mf[0][0..191]
    __shared__ float red_s[8][24];

    if (blockIdx.x >= NPOOLB) {
        // ---- wc block ----
        int c = blockIdx.x - NPOOLB;
        if (threadIdx.x < CC) mf[0][threadIdx.x] = W_emb[(size_t)threadIdx.x * CC + c];
        __syncthreads();
        if (threadIdx.x < CC) {
            int e = threadIdx.x;
            float acc = 0.f;
            #pragma unroll 8
            for (int d = 0; d < CC; d++)
                acc += mf[0][d] * __ldg(&W_gcn[(size_t)d * CC + e]);
            g_Wc[c*CC + e] = acc;
        }
        return;
    }

    // ---- pool block ----
    int pb = blockIdx.x;
    int tb = pb % (TT*BB);        // t*B + b
    int cg = pb / (TT*BB);        // channel group
    int t = tb / BB, b = tb % BB;

    const int* mp = masks + ((size_t)(b*TT + t) * KK) * PIX;
    for (int i = threadIdx.x; i < PIX; i += 256) {
        mf[0][i] = (float)(mp[i] & 1);
        mf[1][i] = (float)(mp[PIX + i] & 1);
        mf[2][i] = (float)(mp[2*PIX + i] & 1);
    }
    __syncthreads();

    const float* xbase = x + ((size_t)(t*BB + b)*CC + cg*CG) * HWPIX;

    float acc[CG][3];
    #pragma unroll
    for (int cc = 0; cc < CG; cc++) {
        acc[cc][0] = 0.f; acc[cc][1] = 0.f; acc[cc][2] = 0.f;
    }

    for (int i4 = threadIdx.x; i4 < HWPIX/4; i4 += 256) {
        int lin = i4 * 4;
        int h = lin / WW;
        int w = lin - h * WW;
        int mb = (h >> 1) * W0 + (w >> 1);
        float2 m0 = *(const float2*)&mf[0][mb];
        float2 m1 = *(const float2*)&mf[1][mb];
        float2 m2 = *(const float2*)&mf[2][mb];
        #pragma unroll
        for (int cc = 0; cc < CG; cc++) {
            float4 v = *(const float4*)(xbase + (size_t)cc*HWPIX + lin);
            float p0 = v.x + v.y, p1 = v.z + v.w;
            acc[cc][0] += p0 * m0.x + p1 * m0.y;
            acc[cc][1] += p0 * m1.x + p1 * m1.y;
            acc[cc][2] += p0 * m2.x + p1 * m2.y;
        }
    }

    int warp = threadIdx.x >> 5, lane = threadIdx.x & 31;
    #pragma unroll
    for (int cc = 0; cc < CG; cc++) {
        #pragma unroll
        for (int k = 0; k < 3; k++) {
            float s = acc[cc][k];
            #pragma unroll
            for (int off = 16; off; off >>= 1)
                s += __shfl_down_sync(0xFFFFFFFFu, s, off);
            if (lane == 0) red_s[warp][cc*3 + k] = s;
        }
    }
    __syncthreads();
    if (threadIdx.x < 24) {
        float s = 0.f;
        #pragma unroll
        for (int w8 = 0; w8 < 8; w8++) s += red_s[w8][threadIdx.x];
        int cc = threadIdx.x / 3, k = threadIdx.x % 3;
        int c = cg * CG + cc;
        g_feat[((size_t)(b*TT + t) * KK + k) * CC + c] = s * (1.0f / (float)HWPIX);
    }
}

// ---------------------------------------------------------------------------
// Kernel 2: full GCN (per-block recompute from L2-resident feat/Wc) ∥ scatter.
// Each block needs only: gram rows n = t*3+{0,1,2} (54 dots), 3 softmaxes,
// sup[m][c] for its 8 c's (144 dots), 24 outk values. ~38K MACs per block,
// hidden under the streaming stream's first-wave latency.
__global__ __launch_bounds__(256) void scatter_kernel(const float* __restrict__ x,
                                                      const int* __restrict__ masks,
                                                      const float* __restrict__ b_gcn,
                                                      float* __restrict__ out) {
    int tb = blockIdx.x;
    int cg = blockIdx.y;
    int t = tb / BB, b = tb % BB;

    __shared__ float mf[3][PIX];
    __shared__ float sup_s[NN][CG];     // 18 x 8
    __shared__ float adj_s[KK][NN];     // 3 x 18 (dots, then softmaxed)
    __shared__ float rs[CG][3];

    int tid = threadIdx.x;

    // phase 0: mask fill (all threads)
    const int* mp = masks + ((size_t)(b*TT + t) * KK) * PIX;
    for (int i = tid; i < PIX; i += 256) {
        mf[0][i] = (float)(mp[i] & 1);
        mf[1][i] = (float)(mp[PIX + i] & 1);
        mf[2][i] = (float)(mp[2*PIX + i] & 1);
    }

    // phase 1: sup (threads 0..143) and gram rows (threads 192..245)
    const float* fb = g_feat + (size_t)b * NN * CC;
    if (tid < NN*CG) {
        int m = tid / CG, cc = tid % CG;
        int c = cg * CG + cc;
        float acc = 0.f;
        const float* frow = fb + m*CC;
        #pragma unroll 4
        for (int c2 = 0; c2 < CC; c2++)
            acc += __ldg(&frow[c2]) * __ldg(&g_Wc[c2*CC + c]);
        sup_s[m][cc] = acc;
    } else if (tid >= 192 && tid < 192 + KK*NN) {
        int j = tid - 192;
        int k = j / NN, m = j % NN;
        int n = t * KK + k;
        float acc = 0.f;
        const float* frn = fb + n*CC;
        const float* frm = fb + m*CC;
        #pragma unroll 4
        for (int c2 = 0; c2 < CC; c2++)
            acc += __ldg(&frn[c2]) * __ldg(&frm[c2]);
        adj_s[k][m] = acc;
    }
    __syncthreads();

    // phase 2: softmax the 3 rows
    if (tid < KK) {
        float mx = -1e30f;
        #pragma unroll
        for (int m = 0; m < NN; m++) mx = fmaxf(mx, adj_s[tid][m]);
        float sm = 0.f;
        #pragma unroll
        for (int m = 0; m < NN; m++) { float e = expf(adj_s[tid][m] - mx); adj_s[tid][m] = e; sm += e; }
        float inv = 1.0f / sm;
        #pragma unroll
        for (int m = 0; m < NN; m++) adj_s[tid][m] *= inv;
    }
    __syncthreads();

    // phase 3: outk for this block's 24 (c,k) pairs
    if (tid < 24) {
        int cc = tid / 3, k = tid % 3;
        int c = cg * CG + cc;
        float acc = __ldg(&b_gcn[c]);
        #pragma unroll
        for (int m = 0; m < NN; m++)
            acc += adj_s[k][m] * sup_s[m][cc];
        rs[cc][k] = acc;
    }
    __syncthreads();

    float r[CG][3];
    #pragma unroll
    for (int cc = 0; cc < CG; cc++) {
        r[cc][0] = rs[cc][0]; r[cc][1] = rs[cc][1]; r[cc][2] = rs[cc][2];
    }

    size_t plane0 = ((size_t)(t*BB + b)*CC + cg*CG) * HWPIX;
    const float* xbase = x + plane0;
    float*       obase = out + plane0;

    for (int i4 = tid; i4 < HWPIX/4; i4 += 256) {
        int lin = i4 * 4;
        int h = lin / WW;
        int w = lin - h * WW;
        int mb = (h >> 1) * W0 + (w >> 1);
        float2 m0 = *(const float2*)&mf[0][mb];
        float2 m1 = *(const float2*)&mf[1][mb];
        float2 m2 = *(const float2*)&mf[2][mb];
        #pragma unroll
        for (int cc = 0; cc < CG; cc++) {
            float4 v = *(const float4*)(xbase + (size_t)cc*HWPIX + lin);
            float c0 = r[cc][0]*m0.x + r[cc][1]*m1.x + r[cc][2]*m2.x;
            float c1 = r[cc][0]*m0.y + r[cc][1]*m1.y + r[cc][2]*m2.y;
            float4 o;
            o.x = v.x + c0; o.y = v.y + c0;
            o.z = v.z + c1; o.w = v.w + c1;
            *(float4*)(obase + (size_t)cc*HWPIX + lin) = o;
        }
    }
}

// ---------------------------------------------------------------------------
extern "C" void kernel_launch(void* const* d_in, const int* in_sizes, int n_in,
                              void* d_out, int out_size) {
    const float* x      = (const float*)d_in[0];
    const int*   masks  = (const int*)  d_in[1];
    const float* W_emb  = (const float*)d_in[2];
    const float* W_gcn  = (const float*)d_in[3];
    const float* b_gcn  = (const float*)d_in[4];
    float* out = (float*)d_out;

    poolwc_kernel<<<NPOOLB + CC, 256>>>(x, masks, W_emb, W_gcn);
    scatter_kernel<<<dim3(TT*BB, CC/CG), 256>>>(x, masks, b_gcn, out);
}

// round 8
// speedup vs baseline: 1.1032x; 1.1032x over previous
#include <cuda_runtime.h>
#include <cuda_bf16.h>
#include <stdint.h>

// Problem constants
#define TT 6
#define BB 8
#define CC 192
#define HH 112
#define WW 112
#define KK 3
#define H0 56
#define W0 56
#define HWPIX (HH*WW)          // 12544
#define PIX (H0*W0)            // 3136
#define NN (TT*KK)             // 18 nodes
#define CG 8                   // channels per block in streaming kernels
#define NPOOLB (TT*BB*(CC/CG)) // 1152 pool blocks

// Scratch (static device globals — no allocation)
__device__ float g_feat[BB*NN*CC];          // node features [B][N=T*K][C]
__device__ float g_Wc[CC*CC];               // W_emb^T @ W_gcn
__device__ float g_adj[BB*NN*NN];           // softmaxed adjacency
__device__ float g_sup[BB*NN*CC];           // node @ Wc

// ---------------------------------------------------------------------------
// Kernel 1: pool ∥ wc in one launch; wc blocks at the grid TAIL so they fill
// the final partial wave instead of displacing pool's first wave (R6 had them
// at the head and lost ~6us of pool DRAM%).
// blocks [0, NPOOLB):          masked adaptive pooling (exact R2 structure)
// blocks [NPOOLB, NPOOLB+CC):  Wc[c][e] = sum_d W_emb[d][c] * W_gcn[d][e]
__global__ __launch_bounds__(256) void poolwc_kernel(const float* __restrict__ x,
                                                     const int* __restrict__ masks,
                                                     const float* __restrict__ W_emb,
                                                     const float* __restrict__ W_gcn) {
    __shared__ float mf[3][PIX];      // pool masks; wc reuses mf[0][0..191]
    __shared__ float red_s[8][24];

    if (blockIdx.x >= NPOOLB) {
        // ---- wc block ----
        int c = blockIdx.x - NPOOLB;
        if (threadIdx.x < CC) mf[0][threadIdx.x] = W_emb[(size_t)threadIdx.x * CC + c];
        __syncthreads();
        if (threadIdx.x < CC) {
            int e = threadIdx.x;
            float acc = 0.f;
            #pragma unroll 8
            for (int d = 0; d < CC; d++)
                acc += mf[0][d] * __ldg(&W_gcn[(size_t)d * CC + e]);
            g_Wc[c*CC + e] = acc;
        }
        return;
    }

    // ---- pool block ----
    int pb = blockIdx.x;
    int tb = pb % (TT*BB);        // t*B + b
    int cg = pb / (TT*BB);        // channel group
    int t = tb / BB, b = tb % BB;

    const int* mp = masks + ((size_t)(b*TT + t) * KK) * PIX;
    for (int i = threadIdx.x; i < PIX; i += 256) {
        mf[0][i] = (float)(mp[i] & 1);
        mf[1][i] = (float)(mp[PIX + i] & 1);
        mf[2][i] = (float)(mp[2*PIX + i] & 1);
    }
    __syncthreads();

    const float* xbase = x + ((size_t)(t*BB + b)*CC + cg*CG) * HWPIX;

    float acc[CG][3];
    #pragma unroll
    for (int cc = 0; cc < CG; cc++) {
        acc[cc][0] = 0.f; acc[cc][1] = 0.f; acc[cc][2] = 0.f;
    }

    for (int i4 = threadIdx.x; i4 < HWPIX/4; i4 += 256) {
        int lin = i4 * 4;
        int h = lin / WW;
        int w = lin - h * WW;
        int mb = (h >> 1) * W0 + (w >> 1);
        float2 m0 = *(const float2*)&mf[0][mb];
        float2 m1 = *(const float2*)&mf[1][mb];
        float2 m2 = *(const float2*)&mf[2][mb];
        #pragma unroll
        for (int cc = 0; cc < CG; cc++) {
            float4 v = *(const float4*)(xbase + (size_t)cc*HWPIX + lin);
            float p0 = v.x + v.y, p1 = v.z + v.w;
            acc[cc][0] += p0 * m0.x + p1 * m0.y;
            acc[cc][1] += p0 * m1.x + p1 * m1.y;
            acc[cc][2] += p0 * m2.x + p1 * m2.y;
        }
    }

    int warp = threadIdx.x >> 5, lane = threadIdx.x & 31;
    #pragma unroll
    for (int cc = 0; cc < CG; cc++) {
        #pragma unroll
        for (int k = 0; k < 3; k++) {
            float s = acc[cc][k];
            #pragma unroll
            for (int off = 16; off; off >>= 1)
                s += __shfl_down_sync(0xFFFFFFFFu, s, off);
            if (lane == 0) red_s[warp][cc*3 + k] = s;
        }
    }
    __syncthreads();
    if (threadIdx.x < 24) {
        float s = 0.f;
        #pragma unroll
        for (int w8 = 0; w8 < 8; w8++) s += red_s[w8][threadIdx.x];
        int cc = threadIdx.x / 3, k = threadIdx.x % 3;
        int c = cg * CG + cc;
        g_feat[((size_t)(b*TT + t) * KK + k) * CC + c] = s * (1.0f / (float)HWPIX);
    }
}

// ---------------------------------------------------------------------------
// GCN kernel S (exact R3/R6 structure): per (n, b) block — gram row + softmax
// -> g_adj row, and sup row = node_n @ Wc -> g_sup. grid (NN, BB) x 192 thr.
__global__ __launch_bounds__(192) void gcn_s_kernel() {
    __shared__ float node_s[NN*CC];
    __shared__ float dots[NN];

    int n = blockIdx.x, b = blockIdx.y;
    int tid = threadIdx.x;
    int warp = tid >> 5, lane = tid & 31;

    const float* fb = g_feat + (size_t)b * NN * CC;
    for (int j = tid; j < NN*CC; j += 192)
        node_s[j] = fb[j];
    __syncthreads();

    // gram row: warp w handles m = w*3 + q (6 warps x 3 = 18)
    #pragma unroll
    for (int q = 0; q < 3; q++) {
        int m = warp * 3 + q;
        float s = 0.f;
        #pragma unroll
        for (int j = 0; j < 6; j++) {
            int c = lane + 32*j;
            s += node_s[n*CC + c] * node_s[m*CC + c];
        }
        #pragma unroll
        for (int off = 16; off; off >>= 1)
            s += __shfl_down_sync(0xFFFFFFFFu, s, off);
        if (lane == 0) dots[m] = s;
    }
    __syncthreads();

    if (tid == 0) {
        float mx = -1e30f;
        #pragma unroll
        for (int m = 0; m < NN; m++) mx = fmaxf(mx, dots[m]);
        float sm = 0.f;
        #pragma unroll
        for (int m = 0; m < NN; m++) { float e = expf(dots[m] - mx); dots[m] = e; sm += e; }
        float inv = 1.0f / sm;
        #pragma unroll
        for (int m = 0; m < NN; m++) dots[m] *= inv;
    }
    __syncthreads();
    if (tid < NN) g_adj[((size_t)b*NN + n)*NN + tid] = dots[tid];

    // sup row: sup[e] = sum_c node_n[c] * Wc[c][e]  (Wc coalesced)
    float acc = 0.f;
    const float* nrow = node_s + n*CC;
    #pragma unroll 4
    for (int c = 0; c < CC; c++)
        acc += nrow[c] * g_Wc[c*CC + tid];
    g_sup[((size_t)b*NN + n)*CC + tid] = acc;
}

// ---------------------------------------------------------------------------
// Kernel 3 (exact R6 structure): gcn_o ∥ residual scatter.
// Threads <24 compute the block's 24 outk values (24 x 18 L2 MACs, hidden
// under warps 1-7's mask smem fill); streaming loop is the known-best form.
__global__ __launch_bounds__(256) void scatter_kernel(const float* __restrict__ x,
                                                      const int* __restrict__ masks,
                                                      const float* __restrict__ b_gcn,
                                                      float* __restrict__ out) {
    int tb = blockIdx.x;
    int cg = blockIdx.y;
    int t = tb / BB, b = tb % BB;

    __shared__ float mf[3][PIX];
    __shared__ float rs[CG][3];

    const int* mp = masks + ((size_t)(b*TT + t) * KK) * PIX;
    if (threadIdx.x >= 32) {
        for (int i = threadIdx.x - 32; i < PIX; i += 224) {
            mf[0][i] = (float)(mp[i] & 1);
            mf[1][i] = (float)(mp[PIX + i] & 1);
            mf[2][i] = (float)(mp[2*PIX + i] & 1);
        }
    } else if (threadIdx.x < 24) {
        // out[b][n][c] = b_gcn[c] + sum_m adj[b][n][m] * sup[b][m][c]
        int cc = threadIdx.x / 3, k = threadIdx.x % 3;
        int c = cg * CG + cc;
        int n = t * KK + k;
        const float* arow = g_adj + ((size_t)b*NN + n)*NN;
        const float* supb = g_sup + (size_t)b*NN*CC + c;
        float acc = __ldg(&b_gcn[c]);
        #pragma unroll
        for (int m = 0; m < NN; m++)
            acc += arow[m] * supb[(size_t)m*CC];
        rs[cc][k] = acc;
    }
    __syncthreads();

    float r[CG][3];
    #pragma unroll
    for (int cc = 0; cc < CG; cc++) {
        r[cc][0] = rs[cc][0]; r[cc][1] = rs[cc][1]; r[cc][2] = rs[cc][2];
    }

    size_t plane0 = ((size_t)(t*BB + b)*CC + cg*CG) * HWPIX;
    const float* xbase = x + plane0;
    float*       obase = out + plane0;

    for (int i4 = threadIdx.x; i4 < HWPIX/4; i4 += 256) {
        int lin = i4 * 4;
        int h = lin / WW;
        int w = lin - h * WW;
        int mb = (h >> 1) * W0 + (w >> 1);
        float2 m0 = *(const float2*)&mf[0][mb];
        float2 m1 = *(const float2*)&mf[1][mb];
        float2 m2 = *(const float2*)&mf[2][mb];
        #pragma unroll
        for (int cc = 0; cc < CG; cc++) {
            float4 v = *(const float4*)(xbase + (size_t)cc*HWPIX + lin);
            float c0 = r[cc][0]*m0.x + r[cc][1]*m1.x + r[cc][2]*m2.x;
            float c1 = r[cc][0]*m0.y + r[cc][1]*m1.y + r[cc][2]*m2.y;
            float4 o;
            o.x = v.x + c0; o.y = v.y + c0;
            o.z = v.z + c1; o.w = v.w + c1;
            *(float4*)(obase + (size_t)cc*HWPIX + lin) = o;
        }
    }
}

// ---------------------------------------------------------------------------
extern "C" void kernel_launch(void* const* d_in, const int* in_sizes, int n_in,
                              void* d_out, int out_size) {
    const float* x      = (const float*)d_in[0];
    const int*   masks  = (const int*)  d_in[1];
    const float* W_emb  = (const float*)d_in[2];
    const float* W_gcn  = (const float*)d_in[3];
    const float* b_gcn  = (const float*)d_in[4];
    float* out = (float*)d_out;

    poolwc_kernel<<<NPOOLB + CC, 256>>>(x, masks, W_emb, W_gcn);
    gcn_s_kernel<<<dim3(NN, BB), 192>>>();
    scatter_kernel<<<dim3(TT*BB, CC/CG), 256>>>(x, masks, b_gcn, out);
}